// round 8
// baseline (speedup 1.0000x reference)
#include <cuda_runtime.h>
#include <cuda_fp16.h>
#include <math.h>
#include <stdint.h>

#define BB 1024
#define VV 50000
#define HH 100
#define KK 200
#define TT 32768
#define BN_EPS 1e-5f
#define VP 50048                  // padded row pitch for y (fp16)

// GEMM1 split-K layout: 18 splits * 44 chunks * 64 = 50688 padded K
#define SPLITS 18
#define NCH 44
#define KSPAN (NCH * 64)          // 2816
#define KP1 (SPLITS * KSPAN)      // 50688
#define VT3 391                   // ceil(50000/128) v-tiles for GEMM3
#define VROWS 50048               // padded v rows for betaT

// ---------------- scratch (__device__ globals: allocation-free, zero-init) -----
__device__ __half g_fc1T[128 * KP1];               // fc1_w^T fp16 (13 MB; rows >=100 zero)
__device__ __half g_betaT[VROWS * KK];             // beta_w^T fp16, K=200 (20 MB)
__device__ __half g_thetab[BB * KK];               // exp(x - rowmax) fp16
__device__ __half g_y[BB * VP];                    // y = theta' @ beta, fp16 (102.5 MB)
__device__ float g_x[BB * KK];                     // pre-exp log-theta (fp32)
__device__ float g_mrow[BB];                       // s_b = exp(rowmax)
__device__ float g_part1[SPLITS * BB * 104];       // GEMM1 split-K partials (7.7 MB)
__device__ float g_h1[BB * HH];
__device__ float g_mulin[BB * KK];
__device__ float g_siglin[BB * KK];
__device__ float g_sep[VT3 * BB];                  // per-vtile se partials
__device__ float g_dotp[VT3 * BB];                 // per-vtile dot partials
__device__ int   g_cnt[VV];

struct __align__(8) HF4 { __half2 lo, hi; };

__device__ __forceinline__ uint32_t smem_u32(const void* p) {
    uint32_t a;
    asm("{ .reg .u64 t; cvta.to.shared.u64 t, %1; cvt.u32.u64 %0, t; }" : "=r"(a) : "l"(p));
    return a;
}

__device__ __forceinline__ float softplusf(float x) {
    return fmaxf(x, 0.f) + log1pf(expf(-fabsf(x)));
}

// ---------------- k16 MMA inner loop (fp16 m16n8k16, direct LDS frags) ----------
// Pitch P (halves) must satisfy (2*P) % 128 == 16. P=72 and P=200 qualify.
template<int P, int NK>
__device__ __forceinline__ void mma_steps(const __half* As, const __half* Bs,
                                          int wm0, int wn0, int gid, int tid4,
                                          float c[2][8][4]) {
    #pragma unroll
    for (int ks = 0; ks < NK; ks++) {
        const int k0 = ks * 16 + 2 * tid4;
        uint32_t a[2][4];
        #pragma unroll
        for (int mt = 0; mt < 2; mt++) {
            int r = wm0 + mt * 16 + gid;
            const uint32_t* p0 = (const uint32_t*)&As[r * P + k0];
            const uint32_t* p1 = (const uint32_t*)&As[(r + 8) * P + k0];
            a[mt][0] = p0[0]; a[mt][1] = p1[0]; a[mt][2] = p0[4]; a[mt][3] = p1[4];
        }
        #pragma unroll
        for (int nt = 0; nt < 8; nt++) {
            const uint32_t* pb = (const uint32_t*)&Bs[(wn0 + nt * 8 + gid) * P + k0];
            uint32_t b0 = pb[0], b1 = pb[4];
            #pragma unroll
            for (int mt = 0; mt < 2; mt++) {
                asm volatile(
                    "mma.sync.aligned.m16n8k16.row.col.f32.f16.f16.f32 "
                    "{%0,%1,%2,%3}, {%4,%5,%6,%7}, {%8,%9}, {%0,%1,%2,%3};"
                    : "+f"(c[mt][nt][0]), "+f"(c[mt][nt][1]),
                      "+f"(c[mt][nt][2]), "+f"(c[mt][nt][3])
                    : "r"(a[mt][0]), "r"(a[mt][1]), "r"(a[mt][2]), "r"(a[mt][3]),
                      "r"(b0), "r"(b1));
            }
        }
    }
}

// ---------------- small kernels -------------------------------------------------
__global__ void k_zero() {
    int v = blockIdx.x * 256 + threadIdx.x;
    if (v < VV) g_cnt[v] = 0;
}
__global__ void k_hist(const int* __restrict__ toks) {
    int t = blockIdx.x * 256 + threadIdx.x;
    if (t < TT) atomicAdd(&g_cnt[toks[t]], 1);
}

// fc1_w [50000,100] -> g_fc1T [128][KP1] fp16 (transpose, zero-padded)
__global__ void k_cvt_fc1(const float* __restrict__ w) {
    __shared__ float t[32][33];
    int k0 = blockIdx.x * 32, h0 = blockIdx.y * 32;
    int tx = threadIdx.x, ty = threadIdx.y;
    #pragma unroll
    for (int j = 0; j < 4; j++) {
        int k = k0 + ty + j * 8, h = h0 + tx;
        t[ty + j * 8][tx] = (k < VV && h < HH) ? w[k * HH + h] : 0.f;
    }
    __syncthreads();
    #pragma unroll
    for (int j = 0; j < 4; j++) {
        int h = h0 + ty + j * 8, k = k0 + tx;
        g_fc1T[h * KP1 + k] = __float2half(t[tx][ty + j * 8]);
    }
}

// beta_w [200,50000] -> g_betaT [VROWS][200] fp16 (transpose; pad rows stay 0)
__global__ void k_cvt_beta(const float* __restrict__ w) {
    __shared__ float t[32][33];
    int v0 = blockIdx.x * 32, k0 = blockIdx.y * 32;
    int tx = threadIdx.x, ty = threadIdx.y;
    #pragma unroll
    for (int j = 0; j < 4; j++) {
        int k = k0 + ty + j * 8, v = v0 + tx;
        t[ty + j * 8][tx] = (k < KK && v < VV) ? w[k * VV + v] : 0.f;
    }
    __syncthreads();
    #pragma unroll
    for (int j = 0; j < 4; j++) {
        int v = v0 + ty + j * 8, k = k0 + tx;
        if (v < VV && k < KK) g_betaT[v * KK + k] = __float2half(t[tx][ty + j * 8]);
    }
}

// ---------------- GEMM1: bows @ fc1 via HMMA, split-K, N=104, double-buffered ---
#define P1 72
#define G1A (128 * P1)
#define G1B (104 * P1)

__global__ void __launch_bounds__(256, 1) k_gemm1(const float* __restrict__ bows) {
    extern __shared__ __half sm1[];
    __half* Abuf[2] = { sm1, sm1 + G1A };
    __half* Bbuf[2] = { sm1 + 2 * G1A, sm1 + 2 * G1A + G1B };

    const int tid = threadIdx.x, wid = tid >> 5, lane = tid & 31;
    const int gid = lane >> 2, tid4 = lane & 3;
    const int wm0 = wid * 16;
    const int m0 = blockIdx.x * 128;
    const int kbase0 = blockIdx.y * KSPAN;

    float c1[13][4] = {};
    float4 ar[8];

    auto loadB = [&](int ch, int buf) {
        #pragma unroll
        for (int j = 0; j < 4; j++) {
            int idx = tid + j * 256;
            if (idx < 832) {    // 104 rows * 8 uint4
                int row = idx >> 3, cc = idx & 7;
                uint32_t dst = smem_u32(&Bbuf[buf][row * P1 + cc * 8]);
                const void* gp = &g_fc1T[row * KP1 + kbase0 + ch * 64 + cc * 8];
                asm volatile("cp.async.cg.shared.global [%0], [%1], 16;" :: "r"(dst), "l"(gp));
            }
        }
        asm volatile("cp.async.commit_group;" ::: "memory");
    };
    auto loadA = [&](int ch) {
        int kb = kbase0 + ch * 64;
        #pragma unroll
        for (int j = 0; j < 8; j++) {
            int idx = tid + j * 256;
            int row = idx >> 4, f4 = idx & 15;
            int k = kb + f4 * 4;
            ar[j] = (k < VV) ? *(const float4*)&bows[(m0 + row) * VV + k]
                             : make_float4(0.f, 0.f, 0.f, 0.f);
        }
    };
    auto stsA = [&](int buf) {
        #pragma unroll
        for (int j = 0; j < 8; j++) {
            int idx = tid + j * 256;
            int row = idx >> 4, f4 = idx & 15;
            HF4 p;
            p.lo = __floats2half2_rn(ar[j].x, ar[j].y);
            p.hi = __floats2half2_rn(ar[j].z, ar[j].w);
            *(HF4*)&Abuf[buf][row * P1 + f4 * 4] = p;
        }
    };

    loadB(0, 0);
    loadA(0);
    stsA(0);
    asm volatile("cp.async.wait_group 0;" ::: "memory");
    __syncthreads();

    for (int ch = 0; ch < NCH; ch++) {
        int cur = ch & 1, nxt = cur ^ 1;
        if (ch + 1 < NCH) { loadB(ch + 1, nxt); loadA(ch + 1); }
        const __half* As = Abuf[cur];
        const __half* Bs = Bbuf[cur];
        #pragma unroll
        for (int ks = 0; ks < 4; ks++) {
            const int k0 = ks * 16 + 2 * tid4;
            const uint32_t* p0 = (const uint32_t*)&As[(wm0 + gid) * P1 + k0];
            const uint32_t* p1 = (const uint32_t*)&As[(wm0 + gid + 8) * P1 + k0];
            uint32_t a0 = p0[0], a1 = p1[0], a2 = p0[4], a3 = p1[4];
            #pragma unroll
            for (int nt = 0; nt < 13; nt++) {
                const uint32_t* pb = (const uint32_t*)&Bs[(nt * 8 + gid) * P1 + k0];
                uint32_t b0 = pb[0], b1 = pb[4];
                asm volatile(
                    "mma.sync.aligned.m16n8k16.row.col.f32.f16.f16.f32 "
                    "{%0,%1,%2,%3}, {%4,%5,%6,%7}, {%8,%9}, {%0,%1,%2,%3};"
                    : "+f"(c1[nt][0]), "+f"(c1[nt][1]), "+f"(c1[nt][2]), "+f"(c1[nt][3])
                    : "r"(a0), "r"(a1), "r"(a2), "r"(a3), "r"(b0), "r"(b1));
            }
        }
        if (ch + 1 < NCH) {
            stsA(nxt);
            asm volatile("cp.async.wait_group 0;" ::: "memory");
        }
        __syncthreads();
    }

    float* dst = &g_part1[(blockIdx.y * BB + m0) * 104];
    #pragma unroll
    for (int nt = 0; nt < 13; nt++) {
        int row = wm0 + gid;
        int col = nt * 8 + 2 * tid4;
        *(float2*)&dst[row * 104 + col]       = make_float2(c1[nt][0], c1[nt][1]);
        *(float2*)&dst[(row + 8) * 104 + col] = make_float2(c1[nt][2], c1[nt][3]);
    }
}

// reduce split-K partials + bias + softplus -> g_h1
__global__ void k_red1(const float* __restrict__ fc1_b) {
    int idx = blockIdx.x * blockDim.x + threadIdx.x;
    if (idx >= BB * HH) return;
    int b = idx / HH, h = idx % HH;
    float s = fc1_b[h];
    #pragma unroll
    for (int p = 0; p < SPLITS; p++) s += g_part1[(p * BB + b) * 104 + h];
    g_h1[idx] = softplusf(s);
}

// ---------------- middle chain (fp32 SIMT, tiny) --------------------------------
__global__ void k_mid(const float* __restrict__ fc2_w, const float* __restrict__ fc2_b,
                      const float* __restrict__ mu_w, const float* __restrict__ sig_w) {
    __shared__ float h1s[16][HH];
    __shared__ float h2s[16][HH];
    int r0 = blockIdx.x * 16;
    int tid = threadIdx.x;
    for (int idx = tid; idx < 16 * HH; idx += 256)
        h1s[idx / HH][idx % HH] = g_h1[(r0 + idx / HH) * HH + idx % HH];
    __syncthreads();
    for (int idx = tid; idx < 16 * HH; idx += 256) {
        int r = idx / HH, h = idx % HH;
        float acc = fc2_b[h];
        #pragma unroll 4
        for (int j = 0; j < HH; j++) acc += h1s[r][j] * fc2_w[j * HH + h];
        h2s[r][h] = softplusf(acc);
    }
    __syncthreads();
    for (int idx = tid; idx < 16 * KK; idx += 256) {
        int r = idx / KK, k = idx % KK;
        float am = 0.f, as = 0.f;
        #pragma unroll 4
        for (int h = 0; h < HH; h++) {
            float x = h2s[r][h];
            am += x * mu_w[h * KK + k];
            as += x * sig_w[h * KK + k];
        }
        g_mulin[(r0 + r) * KK + k]  = am;
        g_siglin[(r0 + r) * KK + k] = as;
    }
}

// ---------------- BN + log-theta x = mu + sigma*eps (fp32). block per k ---------
__global__ void k_theta(const float* __restrict__ eps,
                        const float* __restrict__ bn_mu_g, const float* __restrict__ bn_mu_b,
                        const float* __restrict__ bn_sig_g, const float* __restrict__ bn_sig_b) {
    int k = blockIdx.x;
    int tid = threadIdx.x;
    float xm[4], xs[4];
    float sm = 0.f, sm2 = 0.f, ss = 0.f, ss2 = 0.f;
    #pragma unroll
    for (int i = 0; i < 4; i++) {
        int b = tid + 256 * i;
        xm[i] = g_mulin[b * KK + k];
        xs[i] = g_siglin[b * KK + k];
        sm += xm[i]; sm2 += xm[i] * xm[i];
        ss += xs[i]; ss2 += xs[i] * xs[i];
    }
    #pragma unroll
    for (int off = 16; off; off >>= 1) {
        sm  += __shfl_down_sync(0xffffffffu, sm,  off);
        sm2 += __shfl_down_sync(0xffffffffu, sm2, off);
        ss  += __shfl_down_sync(0xffffffffu, ss,  off);
        ss2 += __shfl_down_sync(0xffffffffu, ss2, off);
    }
    __shared__ float sred[32];
    __shared__ float bc[4];
    int lane = tid & 31, w = tid >> 5;
    if (!lane) { sred[w] = sm; sred[8 + w] = sm2; sred[16 + w] = ss; sred[24 + w] = ss2; }
    __syncthreads();
    if (tid == 0) {
        float m1 = 0, q1 = 0, m2 = 0, q2 = 0;
        for (int i = 0; i < 8; i++) {
            m1 += sred[i]; q1 += sred[8 + i]; m2 += sred[16 + i]; q2 += sred[24 + i];
        }
        m1 *= (1.f / BB); q1 = q1 * (1.f / BB) - m1 * m1;
        m2 *= (1.f / BB); q2 = q2 * (1.f / BB) - m2 * m2;
        bc[0] = m1; bc[1] = rsqrtf(fmaxf(q1, 0.f) + BN_EPS);
        bc[2] = m2; bc[3] = rsqrtf(fmaxf(q2, 0.f) + BN_EPS);
    }
    __syncthreads();
    float gm = bn_mu_g[k], bm = bn_mu_b[k], gs = bn_sig_g[k], bs = bn_sig_b[k];
    #pragma unroll
    for (int i = 0; i < 4; i++) {
        int b = tid + 256 * i;
        float mu = gm * (xm[i] - bc[0]) * bc[1] + bm;
        float sg = expf(0.5f * (gs * (xs[i] - bc[2]) * bc[3] + bs));
        g_x[b * KK + k] = mu + sg * eps[b * KK + k];
    }
}

// ---------------- per-row max + exp -> fp16 theta'; store s_b = exp(max) --------
__global__ void k_rowexp() {
    int b = blockIdx.x;
    int tid = threadIdx.x;   // 64
    float x[4];
    float mx = -1e30f;
    #pragma unroll
    for (int i = 0; i < 4; i++) {
        int k = tid + 64 * i;
        x[i] = (k < KK) ? g_x[b * KK + k] : -1e30f;
        mx = fmaxf(mx, x[i]);
    }
    #pragma unroll
    for (int off = 16; off; off >>= 1)
        mx = fmaxf(mx, __shfl_xor_sync(0xffffffffu, mx, off));
    __shared__ float s[2];
    if ((tid & 31) == 0) s[tid >> 5] = mx;
    __syncthreads();
    float m = fmaxf(s[0], s[1]);
    if (tid == 0) g_mrow[b] = expf(m);
    #pragma unroll
    for (int i = 0; i < 4; i++) {
        int k = tid + 64 * i;
        if (k < KK) g_thetab[b * KK + k] = __float2half(expf(x[i] - m));
    }
}

// ---------------- GEMM3: theta' @ betaT (K=200); fused stats + se/dot pass ------
#define P3 200
#define G3_SMEM (2 * 128 * P3 * 2 + (1024 + 384) * 4)

__global__ void __launch_bounds__(256, 1) k_gemm3(const float* __restrict__ bn_beta_g,
                                                  const float* __restrict__ bn_beta_b) {
    extern __shared__ __half sm3[];
    __half* Bs = sm3;                             // [128][200]
    __half* As = sm3 + 128 * P3;                  // [128][200]
    float* sred = (float*)(sm3 + 2 * 128 * P3);   // 1024 floats
    float* sa = sred + 1024;                      // 128
    float* sc = sa + 128;                         // 128
    float* sn = sc + 128;                         // 128

    const int tid = threadIdx.x, wid = tid >> 5, lane = tid & 31;
    const int gid = lane >> 2, tid4 = lane & 3;
    const int wm0 = (wid & 3) * 32, wn0 = (wid >> 2) * 64;
    const int vt = blockIdx.x;
    const int v0 = vt * 128;

    float st1[16] = {}, st2[16] = {};

    // B tile once: 128 rows x 200 k (25 uint4 per row)
    for (int i = tid; i < 128 * 25; i += 256) {
        int row = i / 25, kv = i % 25;
        *(uint4*)&Bs[row * P3 + kv * 8] = *(const uint4*)&g_betaT[(v0 + row) * KK + kv * 8];
    }

    for (int mt = 0; mt < 8; mt++) {
        const int m0 = mt * 128;
        __syncthreads();
        for (int i = tid; i < 128 * 25; i += 256) {
            int row = i / 25, kv = i % 25;
            *(uint4*)&As[row * P3 + kv * 8] = *(const uint4*)&g_thetab[(m0 + row) * KK + kv * 8];
        }
        __syncthreads();

        float c[2][8][4] = {};
        mma_steps<P3, 12>(As, Bs, wm0, wn0, gid, tid4, c);

        // k8 remainder: k = 192..199
        {
            const int k0r = 192 + 2 * tid4;
            #pragma unroll
            for (int mt2 = 0; mt2 < 2; mt2++) {
                int r = wm0 + mt2 * 16 + gid;
                uint32_t a0 = *(const uint32_t*)&As[r * P3 + k0r];
                uint32_t a1 = *(const uint32_t*)&As[(r + 8) * P3 + k0r];
                #pragma unroll
                for (int nt = 0; nt < 8; nt++) {
                    uint32_t b0 = *(const uint32_t*)&Bs[(wn0 + nt * 8 + gid) * P3 + k0r];
                    asm volatile(
                        "mma.sync.aligned.m16n8k8.row.col.f32.f16.f16.f32 "
                        "{%0,%1,%2,%3}, {%4,%5}, {%6}, {%0,%1,%2,%3};"
                        : "+f"(c[mt2][nt][0]), "+f"(c[mt2][nt][1]),
                          "+f"(c[mt2][nt][2]), "+f"(c[mt2][nt][3])
                        : "r"(a0), "r"(a1), "r"(b0));
                }
            }
        }

        #pragma unroll
        for (int mt2 = 0; mt2 < 2; mt2++) {
            int r0 = m0 + wm0 + mt2 * 16 + gid;
            float s0 = g_mrow[r0];
            float s1 = g_mrow[r0 + 8];
            #pragma unroll
            for (int nt = 0; nt < 8; nt++) {
                int v = v0 + wn0 + nt * 8 + 2 * tid4;
                float y00 = c[mt2][nt][0], y01 = c[mt2][nt][1];
                float y10 = c[mt2][nt][2], y11 = c[mt2][nt][3];
                *(__half2*)&g_y[(size_t)r0 * VP + v]       = __floats2half2_rn(y00, y01);
                *(__half2*)&g_y[(size_t)(r0 + 8) * VP + v] = __floats2half2_rn(y10, y11);
                float t00 = s0 * y00, t01 = s0 * y01;
                float t10 = s1 * y10, t11 = s1 * y11;
                st1[nt * 2]     += t00 + t10;
                st2[nt * 2]     += t00 * t00 + t10 * t10;
                st1[nt * 2 + 1] += t01 + t11;
                st2[nt * 2 + 1] += t01 * t01 + t11 * t11;
            }
        }
    }

    // deterministic stats reduction: gid (shfl) -> warps (smem)
    #pragma unroll
    for (int i = 0; i < 16; i++) {
        #pragma unroll
        for (int off = 16; off >= 4; off >>= 1) {
            st1[i] += __shfl_down_sync(0xffffffffu, st1[i], off);
            st2[i] += __shfl_down_sync(0xffffffffu, st2[i], off);
        }
    }
    if (lane < 4) {
        float* p = &sred[(wid * 4 + lane) * 32];
        #pragma unroll
        for (int i = 0; i < 16; i++) { p[i * 2] = st1[i]; p[i * 2 + 1] = st2[i]; }
    }
    __syncthreads();
    if (tid < 128) {
        int col = tid;
        int grp = col >> 6, nt = (col & 63) >> 3, t4 = (col & 7) >> 1, j = col & 1;
        int idx = nt * 2 + j;
        float s1 = 0.f, s2 = 0.f;
        #pragma unroll
        for (int w2 = 0; w2 < 4; w2++) {
            const float* p = &sred[((4 * grp + w2) * 4 + t4) * 32];
            s1 += p[idx * 2];
            s2 += p[idx * 2 + 1];
        }
        int vg = v0 + col;
        float a = 0.f, cc = -1e30f, nn = 0.f;
        if (vg < VV) {
            float m = s1 * (1.f / BB);
            float var = fmaxf(s2 * (1.f / BB) - m * m, 0.f);
            a = bn_beta_g[vg] * rsqrtf(var + BN_EPS);
            cc = bn_beta_b[vg] - a * m;
            nn = (float)g_cnt[vg];
        }
        sa[col] = a; sc[col] = cc; sn[col] = nn;
    }
    __syncthreads();

    // pass 2: per-row se/dot partials over this CTA's 128 columns (y mostly L2-hot)
    {
        const int l4 = lane * 4;
        float a0 = sa[l4], a1 = sa[l4 + 1], a2 = sa[l4 + 2], a3 = sa[l4 + 3];
        float c0 = sc[l4], c1 = sc[l4 + 1], c2 = sc[l4 + 2], c3 = sc[l4 + 3];
        float n0 = sn[l4], n1 = sn[l4 + 1], n2 = sn[l4 + 2], n3 = sn[l4 + 3];
        for (int i = 0; i < 128; i++) {
            int row = i * 8 + wid;
            float sr = g_mrow[row];
            const __half2* yp = (const __half2*)&g_y[(size_t)row * VP + v0 + l4];
            float2 y01 = __half22float2(yp[0]);
            float2 y23 = __half22float2(yp[1]);
            float nl0 = fmaf(a0, sr * y01.x, c0);
            float nl1 = fmaf(a1, sr * y01.y, c1);
            float nl2 = fmaf(a2, sr * y23.x, c2);
            float nl3 = fmaf(a3, sr * y23.y, c3);
            float se = expf(nl0) + expf(nl1) + expf(nl2) + expf(nl3);
            float dt = n0 * nl0 + n1 * nl1 + n2 * nl2 + n3 * nl3;
            #pragma unroll
            for (int off = 16; off; off >>= 1) {
                se += __shfl_down_sync(0xffffffffu, se, off);
                dt += __shfl_down_sync(0xffffffffu, dt, off);
            }
            if (!lane) {
                g_sep[vt * BB + row]  = se;
                g_dotp[vt * BB + row] = dt;
            }
        }
    }
}

// ---------------- final reduce over 391 vtile partials --------------------------
__global__ void k_final2(float* __restrict__ out) {
    int b = blockIdx.x * 256 + threadIdx.x;
    if (b >= BB) return;
    double S = 0.0, D = 0.0;
    for (int vt = 0; vt < VT3; vt++) {
        S += (double)g_sep[vt * BB + b];
        D += (double)g_dotp[vt * BB + b];
    }
    out[b] = (float)(D - (double)TT * log(S));
}

// ---------------- launch --------------------------------------------------------
extern "C" void kernel_launch(void* const* d_in, const int* in_sizes, int n_in,
                              void* d_out, int out_size) {
    const float* bows      = (const float*)d_in[0];
    const float* eps       = (const float*)d_in[1];
    const int*   toks      = (const int*)  d_in[2];
    const float* fc1_w     = (const float*)d_in[3];
    const float* fc1_b     = (const float*)d_in[4];
    const float* fc2_w     = (const float*)d_in[5];
    const float* fc2_b     = (const float*)d_in[6];
    const float* mu_w      = (const float*)d_in[7];
    const float* bn_mu_g   = (const float*)d_in[9];
    const float* bn_mu_b   = (const float*)d_in[10];
    const float* sig_w     = (const float*)d_in[11];
    const float* bn_sig_g  = (const float*)d_in[13];
    const float* bn_sig_b  = (const float*)d_in[14];
    const float* beta_w    = (const float*)d_in[15];
    const float* bn_beta_g = (const float*)d_in[17];
    const float* bn_beta_b = (const float*)d_in[18];
    float* out = (float*)d_out;

    const int g1_smem = (2 * G1A + 2 * G1B) * (int)sizeof(__half);   // 66816
    cudaFuncSetAttribute(k_gemm1, cudaFuncAttributeMaxDynamicSharedMemorySize, g1_smem);
    cudaFuncSetAttribute(k_gemm3, cudaFuncAttributeMaxDynamicSharedMemorySize, G3_SMEM);

    k_zero<<<(VV + 255) / 256, 256>>>();
    k_hist<<<(TT + 255) / 256, 256>>>(toks);
    k_cvt_fc1<<<dim3(KP1 / 32, 4), dim3(32, 8)>>>(fc1_w);
    k_cvt_beta<<<dim3(1563, 7), dim3(32, 8)>>>(beta_w);
    k_gemm1<<<dim3(8, SPLITS), 256, g1_smem>>>(bows);
    k_red1<<<(BB * HH + 255) / 256, 256>>>(fc1_b);
    k_mid<<<BB / 16, 256>>>(fc2_w, fc2_b, mu_w, sig_w);
    k_theta<<<KK, 256>>>(eps, bn_mu_g, bn_mu_b, bn_sig_g, bn_sig_b);
    k_rowexp<<<BB, 64>>>();
    k_gemm3<<<VT3, 256, G3_SMEM>>>(bn_beta_g, bn_beta_b);
    k_final2<<<4, 256>>>(out);
}

// round 9
// speedup vs baseline: 1.3982x; 1.3982x over previous
#include <cuda_runtime.h>
#include <cuda_fp16.h>
#include <math.h>
#include <stdint.h>

#define BB 1024
#define VV 50000
#define HH 100
#define KK 200
#define TT 32768
#define BN_EPS 1e-5f
#define VP 50048                  // padded row pitch for y (fp16)

// GEMM1 split-K layout: 18 splits * 44 chunks * 64 = 50688 padded K
#define SPLITS 18
#define NCH 44
#define KSPAN (NCH * 64)          // 2816
#define KP1 (SPLITS * KSPAN)      // 50688
#define VT3 391                   // ceil(50000/128) v-tiles for GEMM3
#define VROWS 50048               // padded v rows for betaT

// ---------------- scratch (__device__ globals: allocation-free, zero-init) -----
__device__ __half g_fc1T[128 * KP1];               // fc1_w^T fp16 (13 MB)
__device__ __half g_betaT[VROWS * KK];             // beta_w^T fp16, K=200 (20 MB)
__device__ __half g_thetab[BB * KK];               // exp(x - rowmax) fp16
__device__ __half g_y[BB * VP];                    // y = theta' @ beta, fp16 (102.5 MB)
__device__ float g_x[BB * KK];                     // pre-exp log-theta (fp32)
__device__ float g_mrow[BB];                       // s_b = exp(rowmax)
__device__ float g_part1[SPLITS * BB * 128];       // GEMM1 split-K partials (9.4 MB)
__device__ float g_h1[BB * HH];
__device__ float g_mulin[BB * KK];
__device__ float g_siglin[BB * KK];
__device__ float g_av[VV];
__device__ float g_cv[VV];
__device__ int   g_cnt[VV];

struct __align__(8) HF4 { __half2 lo, hi; };

__device__ __forceinline__ uint32_t smem_u32(const void* p) {
    uint32_t a;
    asm("{ .reg .u64 t; cvta.to.shared.u64 t, %1; cvt.u32.u64 %0, t; }" : "=r"(a) : "l"(p));
    return a;
}

__device__ __forceinline__ float softplusf(float x) {
    return fmaxf(x, 0.f) + log1pf(expf(-fabsf(x)));
}

// ---------------- k16 MMA inner loop (fp16 m16n8k16, direct LDS frags) ----------
// Pitch P (halves) must satisfy (2*P) % 128 == 16. P=72 and P=200 qualify.
template<int P, int NK>
__device__ __forceinline__ void mma_steps(const __half* As, const __half* Bs,
                                          int wm0, int wn0, int gid, int tid4,
                                          float c[2][8][4]) {
    #pragma unroll
    for (int ks = 0; ks < NK; ks++) {
        const int k0 = ks * 16 + 2 * tid4;
        uint32_t a[2][4];
        #pragma unroll
        for (int mt = 0; mt < 2; mt++) {
            int r = wm0 + mt * 16 + gid;
            const uint32_t* p0 = (const uint32_t*)&As[r * P + k0];
            const uint32_t* p1 = (const uint32_t*)&As[(r + 8) * P + k0];
            a[mt][0] = p0[0]; a[mt][1] = p1[0]; a[mt][2] = p0[4]; a[mt][3] = p1[4];
        }
        #pragma unroll
        for (int nt = 0; nt < 8; nt++) {
            const uint32_t* pb = (const uint32_t*)&Bs[(wn0 + nt * 8 + gid) * P + k0];
            uint32_t b0 = pb[0], b1 = pb[4];
            #pragma unroll
            for (int mt = 0; mt < 2; mt++) {
                asm volatile(
                    "mma.sync.aligned.m16n8k16.row.col.f32.f16.f16.f32 "
                    "{%0,%1,%2,%3}, {%4,%5,%6,%7}, {%8,%9}, {%0,%1,%2,%3};"
                    : "+f"(c[mt][nt][0]), "+f"(c[mt][nt][1]),
                      "+f"(c[mt][nt][2]), "+f"(c[mt][nt][3])
                    : "r"(a[mt][0]), "r"(a[mt][1]), "r"(a[mt][2]), "r"(a[mt][3]),
                      "r"(b0), "r"(b1));
            }
        }
    }
}

// ---------------- small kernels -------------------------------------------------
__global__ void k_zero() {
    int v = blockIdx.x * 256 + threadIdx.x;
    if (v < VV) g_cnt[v] = 0;
}
__global__ void k_hist(const int* __restrict__ toks) {
    int t = blockIdx.x * 256 + threadIdx.x;
    if (t < TT) atomicAdd(&g_cnt[toks[t]], 1);
}

// fc1_w [50000,100] -> g_fc1T [128][KP1] fp16 (transpose, zero-padded)
__global__ void k_cvt_fc1(const float* __restrict__ w) {
    __shared__ float t[32][33];
    int k0 = blockIdx.x * 32, h0 = blockIdx.y * 32;
    int tx = threadIdx.x, ty = threadIdx.y;
    #pragma unroll
    for (int j = 0; j < 4; j++) {
        int k = k0 + ty + j * 8, h = h0 + tx;
        t[ty + j * 8][tx] = (k < VV && h < HH) ? w[k * HH + h] : 0.f;
    }
    __syncthreads();
    #pragma unroll
    for (int j = 0; j < 4; j++) {
        int h = h0 + ty + j * 8, k = k0 + tx;
        g_fc1T[h * KP1 + k] = __float2half(t[tx][ty + j * 8]);
    }
}

// beta_w [200,50000] -> g_betaT [VROWS][200] fp16 (transpose; pad rows stay 0)
__global__ void k_cvt_beta(const float* __restrict__ w) {
    __shared__ float t[32][33];
    int v0 = blockIdx.x * 32, k0 = blockIdx.y * 32;
    int tx = threadIdx.x, ty = threadIdx.y;
    #pragma unroll
    for (int j = 0; j < 4; j++) {
        int k = k0 + ty + j * 8, v = v0 + tx;
        t[ty + j * 8][tx] = (k < KK && v < VV) ? w[k * VV + v] : 0.f;
    }
    __syncthreads();
    #pragma unroll
    for (int j = 0; j < 4; j++) {
        int v = v0 + ty + j * 8, k = k0 + tx;
        if (v < VV && k < KK) g_betaT[v * KK + k] = __float2half(t[tx][ty + j * 8]);
    }
}

// ---------------- GEMM1: bows @ fc1 via HMMA, split-K, double-buffered ----------
#define P1 72
#define G1_BUF (128 * P1)

__global__ void __launch_bounds__(256, 1) k_gemm1(const float* __restrict__ bows) {
    extern __shared__ __half sm1[];
    __half* Abuf[2] = { sm1, sm1 + G1_BUF };
    __half* Bbuf[2] = { sm1 + 2 * G1_BUF, sm1 + 3 * G1_BUF };

    const int tid = threadIdx.x, wid = tid >> 5, lane = tid & 31;
    const int gid = lane >> 2, tid4 = lane & 3;
    const int wm0 = (wid & 3) * 32, wn0 = (wid >> 2) * 64;
    const int m0 = blockIdx.x * 128;
    const int kbase0 = blockIdx.y * KSPAN;

    float c[2][8][4] = {};
    float4 ar[8];

    auto loadB = [&](int ch, int buf) {
        #pragma unroll
        for (int j = 0; j < 4; j++) {
            int idx = tid + j * 256;
            int row = idx >> 3, cc = idx & 7;
            uint32_t dst = smem_u32(&Bbuf[buf][row * P1 + cc * 8]);
            const void* gp = &g_fc1T[row * KP1 + kbase0 + ch * 64 + cc * 8];
            asm volatile("cp.async.cg.shared.global [%0], [%1], 16;" :: "r"(dst), "l"(gp));
        }
        asm volatile("cp.async.commit_group;" ::: "memory");
    };
    auto loadA = [&](int ch) {
        int kb = kbase0 + ch * 64;
        #pragma unroll
        for (int j = 0; j < 8; j++) {
            int idx = tid + j * 256;
            int row = idx >> 4, f4 = idx & 15;
            int k = kb + f4 * 4;
            ar[j] = (k < VV) ? *(const float4*)&bows[(m0 + row) * VV + k]
                             : make_float4(0.f, 0.f, 0.f, 0.f);
        }
    };
    auto stsA = [&](int buf) {
        #pragma unroll
        for (int j = 0; j < 8; j++) {
            int idx = tid + j * 256;
            int row = idx >> 4, f4 = idx & 15;
            HF4 p;
            p.lo = __floats2half2_rn(ar[j].x, ar[j].y);
            p.hi = __floats2half2_rn(ar[j].z, ar[j].w);
            *(HF4*)&Abuf[buf][row * P1 + f4 * 4] = p;
        }
    };

    loadB(0, 0);
    loadA(0);
    stsA(0);
    asm volatile("cp.async.wait_group 0;" ::: "memory");
    __syncthreads();

    for (int ch = 0; ch < NCH; ch++) {
        int cur = ch & 1, nxt = cur ^ 1;
        if (ch + 1 < NCH) { loadB(ch + 1, nxt); loadA(ch + 1); }
        mma_steps<P1, 4>(Abuf[cur], Bbuf[cur], wm0, wn0, gid, tid4, c);
        if (ch + 1 < NCH) {
            stsA(nxt);
            asm volatile("cp.async.wait_group 0;" ::: "memory");
        }
        __syncthreads();
    }

    float* dst = &g_part1[(blockIdx.y * BB + m0) * 128];
    #pragma unroll
    for (int mt = 0; mt < 2; mt++) {
        #pragma unroll
        for (int nt = 0; nt < 8; nt++) {
            int row = wm0 + mt * 16 + gid;
            int col = wn0 + nt * 8 + 2 * tid4;
            *(float2*)&dst[row * 128 + col]       = make_float2(c[mt][nt][0], c[mt][nt][1]);
            *(float2*)&dst[(row + 8) * 128 + col] = make_float2(c[mt][nt][2], c[mt][nt][3]);
        }
    }
}

// reduce split-K partials + bias + softplus -> g_h1
__global__ void k_red1(const float* __restrict__ fc1_b) {
    int idx = blockIdx.x * blockDim.x + threadIdx.x;
    if (idx >= BB * HH) return;
    int b = idx / HH, h = idx % HH;
    float s = fc1_b[h];
    #pragma unroll
    for (int p = 0; p < SPLITS; p++) s += g_part1[(p * BB + b) * 128 + h];
    g_h1[idx] = softplusf(s);
}

// ---------------- middle chain (fp32 SIMT, tiny) --------------------------------
__global__ void k_mid(const float* __restrict__ fc2_w, const float* __restrict__ fc2_b,
                      const float* __restrict__ mu_w, const float* __restrict__ sig_w) {
    __shared__ float h1s[16][HH];
    __shared__ float h2s[16][HH];
    int r0 = blockIdx.x * 16;
    int tid = threadIdx.x;
    for (int idx = tid; idx < 16 * HH; idx += 256)
        h1s[idx / HH][idx % HH] = g_h1[(r0 + idx / HH) * HH + idx % HH];
    __syncthreads();
    for (int idx = tid; idx < 16 * HH; idx += 256) {
        int r = idx / HH, h = idx % HH;
        float acc = fc2_b[h];
        #pragma unroll 4
        for (int j = 0; j < HH; j++) acc += h1s[r][j] * fc2_w[j * HH + h];
        h2s[r][h] = softplusf(acc);
    }
    __syncthreads();
    for (int idx = tid; idx < 16 * KK; idx += 256) {
        int r = idx / KK, k = idx % KK;
        float am = 0.f, as = 0.f;
        #pragma unroll 4
        for (int h = 0; h < HH; h++) {
            float x = h2s[r][h];
            am += x * mu_w[h * KK + k];
            as += x * sig_w[h * KK + k];
        }
        g_mulin[(r0 + r) * KK + k]  = am;
        g_siglin[(r0 + r) * KK + k] = as;
    }
}

// ---------------- BN + log-theta x = mu + sigma*eps (fp32). block per k ---------
__global__ void k_theta(const float* __restrict__ eps,
                        const float* __restrict__ bn_mu_g, const float* __restrict__ bn_mu_b,
                        const float* __restrict__ bn_sig_g, const float* __restrict__ bn_sig_b) {
    int k = blockIdx.x;
    int tid = threadIdx.x;
    float xm[4], xs[4];
    float sm = 0.f, sm2 = 0.f, ss = 0.f, ss2 = 0.f;
    #pragma unroll
    for (int i = 0; i < 4; i++) {
        int b = tid + 256 * i;
        xm[i] = g_mulin[b * KK + k];
        xs[i] = g_siglin[b * KK + k];
        sm += xm[i]; sm2 += xm[i] * xm[i];
        ss += xs[i]; ss2 += xs[i] * xs[i];
    }
    #pragma unroll
    for (int off = 16; off; off >>= 1) {
        sm  += __shfl_down_sync(0xffffffffu, sm,  off);
        sm2 += __shfl_down_sync(0xffffffffu, sm2, off);
        ss  += __shfl_down_sync(0xffffffffu, ss,  off);
        ss2 += __shfl_down_sync(0xffffffffu, ss2, off);
    }
    __shared__ float sred[32];
    __shared__ float bc[4];
    int lane = tid & 31, w = tid >> 5;
    if (!lane) { sred[w] = sm; sred[8 + w] = sm2; sred[16 + w] = ss; sred[24 + w] = ss2; }
    __syncthreads();
    if (tid == 0) {
        float m1 = 0, q1 = 0, m2 = 0, q2 = 0;
        for (int i = 0; i < 8; i++) {
            m1 += sred[i]; q1 += sred[8 + i]; m2 += sred[16 + i]; q2 += sred[24 + i];
        }
        m1 *= (1.f / BB); q1 = q1 * (1.f / BB) - m1 * m1;
        m2 *= (1.f / BB); q2 = q2 * (1.f / BB) - m2 * m2;
        bc[0] = m1; bc[1] = rsqrtf(fmaxf(q1, 0.f) + BN_EPS);
        bc[2] = m2; bc[3] = rsqrtf(fmaxf(q2, 0.f) + BN_EPS);
    }
    __syncthreads();
    float gm = bn_mu_g[k], bm = bn_mu_b[k], gs = bn_sig_g[k], bs = bn_sig_b[k];
    #pragma unroll
    for (int i = 0; i < 4; i++) {
        int b = tid + 256 * i;
        float mu = gm * (xm[i] - bc[0]) * bc[1] + bm;
        float sg = expf(0.5f * (gs * (xs[i] - bc[2]) * bc[3] + bs));
        g_x[b * KK + k] = mu + sg * eps[b * KK + k];
    }
}

// ---------------- per-row max + exp -> fp16 theta'; store s_b = exp(max) --------
__global__ void k_rowexp() {
    int b = blockIdx.x;
    int tid = threadIdx.x;   // 64
    float x[4];
    float mx = -1e30f;
    #pragma unroll
    for (int i = 0; i < 4; i++) {
        int k = tid + 64 * i;
        x[i] = (k < KK) ? g_x[b * KK + k] : -1e30f;
        mx = fmaxf(mx, x[i]);
    }
    #pragma unroll
    for (int off = 16; off; off >>= 1)
        mx = fmaxf(mx, __shfl_xor_sync(0xffffffffu, mx, off));
    __shared__ float s[2];
    if ((tid & 31) == 0) s[tid >> 5] = mx;
    __syncthreads();
    float m = fmaxf(s[0], s[1]);
    if (tid == 0) g_mrow[b] = expf(m);
    #pragma unroll
    for (int i = 0; i < 4; i++) {
        int k = tid + 64 * i;
        if (k < KK) g_thetab[b * KK + k] = __float2half(expf(x[i] - m));
    }
}

// ---------------- GEMM3: theta' @ betaT (K=200); fused column BN stats ----------
#define P3 200
#define G3_SMEM (2 * 128 * P3 * 2 + 1024 * 4)

__global__ void __launch_bounds__(256, 1) k_gemm3(const float* __restrict__ bn_beta_g,
                                                  const float* __restrict__ bn_beta_b) {
    extern __shared__ __half sm3[];
    __half* Bs = sm3;                             // [128][200]
    __half* As = sm3 + 128 * P3;                  // [128][200]
    float* sred = (float*)(sm3 + 2 * 128 * P3);   // 1024 floats

    const int tid = threadIdx.x, wid = tid >> 5, lane = tid & 31;
    const int gid = lane >> 2, tid4 = lane & 3;
    const int wm0 = (wid & 3) * 32, wn0 = (wid >> 2) * 64;
    const int v0 = blockIdx.x * 128;

    float st1[16] = {}, st2[16] = {};

    // B tile once: 128 rows x 200 k (25 uint4 per row)
    for (int i = tid; i < 128 * 25; i += 256) {
        int row = i / 25, kv = i % 25;
        *(uint4*)&Bs[row * P3 + kv * 8] = *(const uint4*)&g_betaT[(v0 + row) * KK + kv * 8];
    }

    for (int mt = 0; mt < 8; mt++) {
        const int m0 = mt * 128;
        __syncthreads();
        for (int i = tid; i < 128 * 25; i += 256) {
            int row = i / 25, kv = i % 25;
            *(uint4*)&As[row * P3 + kv * 8] = *(const uint4*)&g_thetab[(m0 + row) * KK + kv * 8];
        }
        __syncthreads();

        float c[2][8][4] = {};
        mma_steps<P3, 12>(As, Bs, wm0, wn0, gid, tid4, c);

        // k8 remainder: k = 192..199 (validated: bit-identical rel_err in R8)
        {
            const int k0r = 192 + 2 * tid4;
            #pragma unroll
            for (int mt2 = 0; mt2 < 2; mt2++) {
                int r = wm0 + mt2 * 16 + gid;
                uint32_t a0 = *(const uint32_t*)&As[r * P3 + k0r];
                uint32_t a1 = *(const uint32_t*)&As[(r + 8) * P3 + k0r];
                #pragma unroll
                for (int nt = 0; nt < 8; nt++) {
                    uint32_t b0 = *(const uint32_t*)&Bs[(wn0 + nt * 8 + gid) * P3 + k0r];
                    asm volatile(
                        "mma.sync.aligned.m16n8k8.row.col.f32.f16.f16.f32 "
                        "{%0,%1,%2,%3}, {%4,%5}, {%6}, {%0,%1,%2,%3};"
                        : "+f"(c[mt2][nt][0]), "+f"(c[mt2][nt][1]),
                          "+f"(c[mt2][nt][2]), "+f"(c[mt2][nt][3])
                        : "r"(a0), "r"(a1), "r"(b0));
                }
            }
        }

        #pragma unroll
        for (int mt2 = 0; mt2 < 2; mt2++) {
            int r0 = m0 + wm0 + mt2 * 16 + gid;
            float s0 = g_mrow[r0];
            float s1 = g_mrow[r0 + 8];
            #pragma unroll
            for (int nt = 0; nt < 8; nt++) {
                int v = v0 + wn0 + nt * 8 + 2 * tid4;
                float y00 = c[mt2][nt][0], y01 = c[mt2][nt][1];
                float y10 = c[mt2][nt][2], y11 = c[mt2][nt][3];
                *(__half2*)&g_y[(size_t)r0 * VP + v]       = __floats2half2_rn(y00, y01);
                *(__half2*)&g_y[(size_t)(r0 + 8) * VP + v] = __floats2half2_rn(y10, y11);
                float t00 = s0 * y00, t01 = s0 * y01;
                float t10 = s1 * y10, t11 = s1 * y11;
                st1[nt * 2]     += t00 + t10;
                st2[nt * 2]     += t00 * t00 + t10 * t10;
                st1[nt * 2 + 1] += t01 + t11;
                st2[nt * 2 + 1] += t01 * t01 + t11 * t11;
            }
        }
    }

    // deterministic stats reduction: gid (shfl) -> warps (smem)
    #pragma unroll
    for (int i = 0; i < 16; i++) {
        #pragma unroll
        for (int off = 16; off >= 4; off >>= 1) {
            st1[i] += __shfl_down_sync(0xffffffffu, st1[i], off);
            st2[i] += __shfl_down_sync(0xffffffffu, st2[i], off);
        }
    }
    if (lane < 4) {
        float* p = &sred[(wid * 4 + lane) * 32];
        #pragma unroll
        for (int i = 0; i < 16; i++) { p[i * 2] = st1[i]; p[i * 2 + 1] = st2[i]; }
    }
    __syncthreads();
    if (tid < 128) {
        int col = tid;
        int grp = col >> 6, nt = (col & 63) >> 3, t4 = (col & 7) >> 1, j = col & 1;
        int idx = nt * 2 + j;
        float s1 = 0.f, s2 = 0.f;
        #pragma unroll
        for (int w2 = 0; w2 < 4; w2++) {
            const float* p = &sred[((4 * grp + w2) * 4 + t4) * 32];
            s1 += p[idx * 2];
            s2 += p[idx * 2 + 1];
        }
        int vg = v0 + col;
        if (vg < VV) {
            float m = s1 * (1.f / BB);
            float var = fmaxf(s2 * (1.f / BB) - m * m, 0.f);
            float a = bn_beta_g[vg] * rsqrtf(var + BN_EPS);
            g_av[vg] = a;
            g_cv[vg] = bn_beta_b[vg] - a * m;
        }
    }
}

// ---------------- final: lse + histogram dot, 8 rows per CTA --------------------
__global__ void __launch_bounds__(256) k_final(float* __restrict__ out) {
    const int b0 = blockIdx.x * 8;
    const int tid = threadIdx.x;
    float se[8] = {}, dot[8] = {};
    float sr[8];
    #pragma unroll
    for (int r = 0; r < 8; r++) sr[r] = g_mrow[b0 + r];

    for (int v0 = 0; v0 < VP; v0 += 512) {
        int v = v0 + 2 * tid;
        if (v >= VV) continue;   // VV even, v even -> pair fully valid or fully skipped
        float a0 = g_av[v],  a1 = g_av[v + 1];
        float c0 = g_cv[v],  c1 = g_cv[v + 1];
        float n0 = (float)g_cnt[v], n1 = (float)g_cnt[v + 1];
        #pragma unroll
        for (int r = 0; r < 8; r++) {
            float2 yf = __half22float2(*(const __half2*)&g_y[(size_t)(b0 + r) * VP + v]);
            float nl0 = fmaf(a0, sr[r] * yf.x, c0);
            float nl1 = fmaf(a1, sr[r] * yf.y, c1);
            se[r]  += expf(nl0) + expf(nl1);
            dot[r] += n0 * nl0 + n1 * nl1;
        }
    }

    #pragma unroll
    for (int r = 0; r < 8; r++) {
        #pragma unroll
        for (int off = 16; off; off >>= 1) {
            se[r]  += __shfl_down_sync(0xffffffffu, se[r],  off);
            dot[r] += __shfl_down_sync(0xffffffffu, dot[r], off);
        }
    }
    __shared__ double sdr[8][8][2];
    int lane = tid & 31, w = tid >> 5;
    if (!lane) {
        #pragma unroll
        for (int r = 0; r < 8; r++) { sdr[w][r][0] = (double)se[r]; sdr[w][r][1] = (double)dot[r]; }
    }
    __syncthreads();
    if (tid < 8) {
        double S = 0.0, D = 0.0;
        for (int w2 = 0; w2 < 8; w2++) { S += sdr[w2][tid][0]; D += sdr[w2][tid][1]; }
        out[b0 + tid] = (float)(D - (double)TT * log(S));
    }
}

// ---------------- launch --------------------------------------------------------
extern "C" void kernel_launch(void* const* d_in, const int* in_sizes, int n_in,
                              void* d_out, int out_size) {
    const float* bows      = (const float*)d_in[0];
    const float* eps       = (const float*)d_in[1];
    const int*   toks      = (const int*)  d_in[2];
    const float* fc1_w     = (const float*)d_in[3];
    const float* fc1_b     = (const float*)d_in[4];
    const float* fc2_w     = (const float*)d_in[5];
    const float* fc2_b     = (const float*)d_in[6];
    const float* mu_w      = (const float*)d_in[7];
    const float* bn_mu_g   = (const float*)d_in[9];
    const float* bn_mu_b   = (const float*)d_in[10];
    const float* sig_w     = (const float*)d_in[11];
    const float* bn_sig_g  = (const float*)d_in[13];
    const float* bn_sig_b  = (const float*)d_in[14];
    const float* beta_w    = (const float*)d_in[15];
    const float* bn_beta_g = (const float*)d_in[17];
    const float* bn_beta_b = (const float*)d_in[18];
    float* out = (float*)d_out;

    const int g1_smem = 4 * G1_BUF * (int)sizeof(__half);       // 73728
    cudaFuncSetAttribute(k_gemm1, cudaFuncAttributeMaxDynamicSharedMemorySize, g1_smem);
    cudaFuncSetAttribute(k_gemm3, cudaFuncAttributeMaxDynamicSharedMemorySize, G3_SMEM);

    k_zero<<<(VV + 255) / 256, 256>>>();
    k_hist<<<(TT + 255) / 256, 256>>>(toks);
    k_cvt_fc1<<<dim3(KP1 / 32, 4), dim3(32, 8)>>>(fc1_w);
    k_cvt_beta<<<dim3(1563, 7), dim3(32, 8)>>>(beta_w);
    k_gemm1<<<dim3(8, SPLITS), 256, g1_smem>>>(bows);
    k_red1<<<(BB * HH + 255) / 256, 256>>>(fc1_b);
    k_mid<<<BB / 16, 256>>>(fc2_w, fc2_b, mu_w, sig_w);
    k_theta<<<KK, 256>>>(eps, bn_mu_g, bn_mu_b, bn_sig_g, bn_sig_b);
    k_rowexp<<<BB, 64>>>();
    k_gemm3<<<VT3, 256, G3_SMEM>>>(bn_beta_g, bn_beta_b);
    k_final<<<128, 256>>>(out);
}

// round 10
// speedup vs baseline: 1.5216x; 1.0882x over previous
#include <cuda_runtime.h>
#include <cuda_fp16.h>
#include <math.h>
#include <stdint.h>

#define BB 1024
#define VV 50000
#define HH 100
#define KK 200
#define TT 32768
#define BN_EPS 1e-5f
#define VP 50048                  // padded row pitch for y (fp16)

// GEMM1 split-K layout: 36 splits * 22 chunks * 64 = 50688 padded K
#define SPLITS 36
#define NCH 22
#define KSPAN (NCH * 64)          // 1408
#define KP1 (SPLITS * KSPAN)      // 50688
#define VT3 391                   // ceil(50000/128) v-tiles for GEMM3
#define VROWS 50048               // padded v rows for betaT

// ---------------- scratch (__device__ globals: allocation-free, zero-init) -----
__device__ __half g_fc1T[128 * KP1];               // fc1_w^T fp16 (13 MB)
__device__ __half g_betaT[VROWS * KK];             // beta_w^T fp16, K=200 (20 MB)
__device__ __half g_thetab[BB * KK];               // exp(x - rowmax) fp16
__device__ __half g_y[BB * VP];                    // y = theta' @ beta, fp16 (102.5 MB)
__device__ float g_x[BB * KK];                     // pre-exp log-theta (fp32)
__device__ float g_mrow[BB];                       // s_b = exp(rowmax)
__device__ float g_part1[SPLITS * BB * 128];       // GEMM1 split-K partials (18.9 MB)
__device__ float g_h1[BB * HH];
__device__ float g_mulin[BB * KK];
__device__ float g_siglin[BB * KK];
__device__ float g_av[VV];
__device__ float g_cv[VV];
__device__ int   g_cnt[VV];

struct __align__(8) HF4 { __half2 lo, hi; };

__device__ __forceinline__ uint32_t smem_u32(const void* p) {
    uint32_t a;
    asm("{ .reg .u64 t; cvta.to.shared.u64 t, %1; cvt.u32.u64 %0, t; }" : "=r"(a) : "l"(p));
    return a;
}

__device__ __forceinline__ float softplusf(float x) {
    return fmaxf(x, 0.f) + log1pf(expf(-fabsf(x)));
}

// ---------------- k16 MMA inner loop (fp16 m16n8k16, direct LDS frags) ----------
// Pitch P (halves) must satisfy (2*P) % 128 == 16. P=72 and P=200 qualify.
template<int P, int NK>
__device__ __forceinline__ void mma_steps(const __half* As, const __half* Bs,
                                          int wm0, int wn0, int gid, int tid4,
                                          float c[2][8][4]) {
    #pragma unroll
    for (int ks = 0; ks < NK; ks++) {
        const int k0 = ks * 16 + 2 * tid4;
        uint32_t a[2][4];
        #pragma unroll
        for (int mt = 0; mt < 2; mt++) {
            int r = wm0 + mt * 16 + gid;
            const uint32_t* p0 = (const uint32_t*)&As[r * P + k0];
            const uint32_t* p1 = (const uint32_t*)&As[(r + 8) * P + k0];
            a[mt][0] = p0[0]; a[mt][1] = p1[0]; a[mt][2] = p0[4]; a[mt][3] = p1[4];
        }
        #pragma unroll
        for (int nt = 0; nt < 8; nt++) {
            const uint32_t* pb = (const uint32_t*)&Bs[(wn0 + nt * 8 + gid) * P + k0];
            uint32_t b0 = pb[0], b1 = pb[4];
            #pragma unroll
            for (int mt = 0; mt < 2; mt++) {
                asm volatile(
                    "mma.sync.aligned.m16n8k16.row.col.f32.f16.f16.f32 "
                    "{%0,%1,%2,%3}, {%4,%5,%6,%7}, {%8,%9}, {%0,%1,%2,%3};"
                    : "+f"(c[mt][nt][0]), "+f"(c[mt][nt][1]),
                      "+f"(c[mt][nt][2]), "+f"(c[mt][nt][3])
                    : "r"(a[mt][0]), "r"(a[mt][1]), "r"(a[mt][2]), "r"(a[mt][3]),
                      "r"(b0), "r"(b1));
            }
        }
    }
}

// ---------------- small kernels -------------------------------------------------
__global__ void k_zero() {
    int v = blockIdx.x * 256 + threadIdx.x;
    if (v < VV) g_cnt[v] = 0;
}
__global__ void k_hist(const int* __restrict__ toks) {
    int t = blockIdx.x * 256 + threadIdx.x;
    if (t < TT) atomicAdd(&g_cnt[toks[t]], 1);
}

// fc1_w [50000,100] -> g_fc1T [128][KP1] fp16 (transpose, zero-padded)
__global__ void k_cvt_fc1(const float* __restrict__ w) {
    __shared__ float t[32][33];
    int k0 = blockIdx.x * 32, h0 = blockIdx.y * 32;
    int tx = threadIdx.x, ty = threadIdx.y;
    #pragma unroll
    for (int j = 0; j < 4; j++) {
        int k = k0 + ty + j * 8, h = h0 + tx;
        t[ty + j * 8][tx] = (k < VV && h < HH) ? w[k * HH + h] : 0.f;
    }
    __syncthreads();
    #pragma unroll
    for (int j = 0; j < 4; j++) {
        int h = h0 + ty + j * 8, k = k0 + tx;
        g_fc1T[h * KP1 + k] = __float2half(t[tx][ty + j * 8]);
    }
}

// beta_w [200,50000] -> g_betaT [VROWS][200] fp16 (transpose; pad rows stay 0)
__global__ void k_cvt_beta(const float* __restrict__ w) {
    __shared__ float t[32][33];
    int v0 = blockIdx.x * 32, k0 = blockIdx.y * 32;
    int tx = threadIdx.x, ty = threadIdx.y;
    #pragma unroll
    for (int j = 0; j < 4; j++) {
        int k = k0 + ty + j * 8, v = v0 + tx;
        t[ty + j * 8][tx] = (k < KK && v < VV) ? w[k * VV + v] : 0.f;
    }
    __syncthreads();
    #pragma unroll
    for (int j = 0; j < 4; j++) {
        int v = v0 + ty + j * 8, k = k0 + tx;
        if (v < VV && k < KK) g_betaT[v * KK + k] = __float2half(t[tx][ty + j * 8]);
    }
}

// ---------------- GEMM1: bows @ fc1 via HMMA, split-K, 2 CTAs/SM ---------------
#define P1 72
#define G1_BUF (128 * P1)

__global__ void __launch_bounds__(256, 2) k_gemm1(const float* __restrict__ bows) {
    extern __shared__ __half sm1[];
    __half* Abuf[2] = { sm1, sm1 + G1_BUF };
    __half* Bbuf[2] = { sm1 + 2 * G1_BUF, sm1 + 3 * G1_BUF };

    const int tid = threadIdx.x, wid = tid >> 5, lane = tid & 31;
    const int gid = lane >> 2, tid4 = lane & 3;
    const int wm0 = (wid & 3) * 32, wn0 = (wid >> 2) * 64;
    const int m0 = blockIdx.x * 128;
    const int kbase0 = blockIdx.y * KSPAN;

    float c[2][8][4] = {};
    float4 ar[8];

    auto loadB = [&](int ch, int buf) {
        #pragma unroll
        for (int j = 0; j < 4; j++) {
            int idx = tid + j * 256;
            int row = idx >> 3, cc = idx & 7;
            uint32_t dst = smem_u32(&Bbuf[buf][row * P1 + cc * 8]);
            const void* gp = &g_fc1T[row * KP1 + kbase0 + ch * 64 + cc * 8];
            asm volatile("cp.async.cg.shared.global [%0], [%1], 16;" :: "r"(dst), "l"(gp));
        }
        asm volatile("cp.async.commit_group;" ::: "memory");
    };
    auto loadA = [&](int ch) {
        int kb = kbase0 + ch * 64;
        #pragma unroll
        for (int j = 0; j < 8; j++) {
            int idx = tid + j * 256;
            int row = idx >> 4, f4 = idx & 15;
            int k = kb + f4 * 4;
            ar[j] = (k < VV) ? *(const float4*)&bows[(m0 + row) * VV + k]
                             : make_float4(0.f, 0.f, 0.f, 0.f);
        }
    };
    auto stsA = [&](int buf) {
        #pragma unroll
        for (int j = 0; j < 8; j++) {
            int idx = tid + j * 256;
            int row = idx >> 4, f4 = idx & 15;
            HF4 p;
            p.lo = __floats2half2_rn(ar[j].x, ar[j].y);
            p.hi = __floats2half2_rn(ar[j].z, ar[j].w);
            *(HF4*)&Abuf[buf][row * P1 + f4 * 4] = p;
        }
    };

    loadB(0, 0);
    loadA(0);
    stsA(0);
    asm volatile("cp.async.wait_group 0;" ::: "memory");
    __syncthreads();

    for (int ch = 0; ch < NCH; ch++) {
        int cur = ch & 1, nxt = cur ^ 1;
        if (ch + 1 < NCH) { loadB(ch + 1, nxt); loadA(ch + 1); }
        mma_steps<P1, 4>(Abuf[cur], Bbuf[cur], wm0, wn0, gid, tid4, c);
        if (ch + 1 < NCH) {
            stsA(nxt);
            asm volatile("cp.async.wait_group 0;" ::: "memory");
        }
        __syncthreads();
    }

    float* dst = &g_part1[(blockIdx.y * BB + m0) * 128];
    #pragma unroll
    for (int mt = 0; mt < 2; mt++) {
        #pragma unroll
        for (int nt = 0; nt < 8; nt++) {
            int row = wm0 + mt * 16 + gid;
            int col = wn0 + nt * 8 + 2 * tid4;
            *(float2*)&dst[row * 128 + col]       = make_float2(c[mt][nt][0], c[mt][nt][1]);
            *(float2*)&dst[(row + 8) * 128 + col] = make_float2(c[mt][nt][2], c[mt][nt][3]);
        }
    }
}

// reduce split-K partials + bias + softplus -> g_h1
__global__ void k_red1(const float* __restrict__ fc1_b) {
    int idx = blockIdx.x * blockDim.x + threadIdx.x;
    if (idx >= BB * HH) return;
    int b = idx / HH, h = idx % HH;
    float s = fc1_b[h];
    #pragma unroll
    for (int p = 0; p < SPLITS; p++) s += g_part1[(p * BB + b) * 128 + h];
    g_h1[idx] = softplusf(s);
}

// ---------------- middle chain (fp32 SIMT, tiny) --------------------------------
__global__ void k_mid(const float* __restrict__ fc2_w, const float* __restrict__ fc2_b,
                      const float* __restrict__ mu_w, const float* __restrict__ sig_w) {
    __shared__ float h1s[16][HH];
    __shared__ float h2s[16][HH];
    int r0 = blockIdx.x * 16;
    int tid = threadIdx.x;
    for (int idx = tid; idx < 16 * HH; idx += 256)
        h1s[idx / HH][idx % HH] = g_h1[(r0 + idx / HH) * HH + idx % HH];
    __syncthreads();
    for (int idx = tid; idx < 16 * HH; idx += 256) {
        int r = idx / HH, h = idx % HH;
        float acc = fc2_b[h];
        #pragma unroll 4
        for (int j = 0; j < HH; j++) acc += h1s[r][j] * fc2_w[j * HH + h];
        h2s[r][h] = softplusf(acc);
    }
    __syncthreads();
    for (int idx = tid; idx < 16 * KK; idx += 256) {
        int r = idx / KK, k = idx % KK;
        float am = 0.f, as = 0.f;
        #pragma unroll 4
        for (int h = 0; h < HH; h++) {
            float x = h2s[r][h];
            am += x * mu_w[h * KK + k];
            as += x * sig_w[h * KK + k];
        }
        g_mulin[(r0 + r) * KK + k]  = am;
        g_siglin[(r0 + r) * KK + k] = as;
    }
}

// ---------------- BN + log-theta x = mu + sigma*eps (fp32). block per k ---------
__global__ void k_theta(const float* __restrict__ eps,
                        const float* __restrict__ bn_mu_g, const float* __restrict__ bn_mu_b,
                        const float* __restrict__ bn_sig_g, const float* __restrict__ bn_sig_b) {
    int k = blockIdx.x;
    int tid = threadIdx.x;
    float xm[4], xs[4];
    float sm = 0.f, sm2 = 0.f, ss = 0.f, ss2 = 0.f;
    #pragma unroll
    for (int i = 0; i < 4; i++) {
        int b = tid + 256 * i;
        xm[i] = g_mulin[b * KK + k];
        xs[i] = g_siglin[b * KK + k];
        sm += xm[i]; sm2 += xm[i] * xm[i];
        ss += xs[i]; ss2 += xs[i] * xs[i];
    }
    #pragma unroll
    for (int off = 16; off; off >>= 1) {
        sm  += __shfl_down_sync(0xffffffffu, sm,  off);
        sm2 += __shfl_down_sync(0xffffffffu, sm2, off);
        ss  += __shfl_down_sync(0xffffffffu, ss,  off);
        ss2 += __shfl_down_sync(0xffffffffu, ss2, off);
    }
    __shared__ float sred[32];
    __shared__ float bc[4];
    int lane = tid & 31, w = tid >> 5;
    if (!lane) { sred[w] = sm; sred[8 + w] = sm2; sred[16 + w] = ss; sred[24 + w] = ss2; }
    __syncthreads();
    if (tid == 0) {
        float m1 = 0, q1 = 0, m2 = 0, q2 = 0;
        for (int i = 0; i < 8; i++) {
            m1 += sred[i]; q1 += sred[8 + i]; m2 += sred[16 + i]; q2 += sred[24 + i];
        }
        m1 *= (1.f / BB); q1 = q1 * (1.f / BB) - m1 * m1;
        m2 *= (1.f / BB); q2 = q2 * (1.f / BB) - m2 * m2;
        bc[0] = m1; bc[1] = rsqrtf(fmaxf(q1, 0.f) + BN_EPS);
        bc[2] = m2; bc[3] = rsqrtf(fmaxf(q2, 0.f) + BN_EPS);
    }
    __syncthreads();
    float gm = bn_mu_g[k], bm = bn_mu_b[k], gs = bn_sig_g[k], bs = bn_sig_b[k];
    #pragma unroll
    for (int i = 0; i < 4; i++) {
        int b = tid + 256 * i;
        float mu = gm * (xm[i] - bc[0]) * bc[1] + bm;
        float sg = expf(0.5f * (gs * (xs[i] - bc[2]) * bc[3] + bs));
        g_x[b * KK + k] = mu + sg * eps[b * KK + k];
    }
}

// ---------------- per-row max + exp -> fp16 theta'; store s_b = exp(max) --------
__global__ void k_rowexp() {
    int b = blockIdx.x;
    int tid = threadIdx.x;   // 64
    float x[4];
    float mx = -1e30f;
    #pragma unroll
    for (int i = 0; i < 4; i++) {
        int k = tid + 64 * i;
        x[i] = (k < KK) ? g_x[b * KK + k] : -1e30f;
        mx = fmaxf(mx, x[i]);
    }
    #pragma unroll
    for (int off = 16; off; off >>= 1)
        mx = fmaxf(mx, __shfl_xor_sync(0xffffffffu, mx, off));
    __shared__ float s[2];
    if ((tid & 31) == 0) s[tid >> 5] = mx;
    __syncthreads();
    float m = fmaxf(s[0], s[1]);
    if (tid == 0) g_mrow[b] = expf(m);
    #pragma unroll
    for (int i = 0; i < 4; i++) {
        int k = tid + 64 * i;
        if (k < KK) g_thetab[b * KK + k] = __float2half(expf(x[i] - m));
    }
}

// ---------------- GEMM3: theta' @ betaT (K=200); fused column BN stats ----------
#define P3 200
#define G3_SMEM (2 * 128 * P3 * 2 + 1024 * 4)

__global__ void __launch_bounds__(256, 1) k_gemm3(const float* __restrict__ bn_beta_g,
                                                  const float* __restrict__ bn_beta_b) {
    extern __shared__ __half sm3[];
    __half* Bs = sm3;                             // [128][200]
    __half* As = sm3 + 128 * P3;                  // [128][200]
    float* sred = (float*)(sm3 + 2 * 128 * P3);   // 1024 floats

    const int tid = threadIdx.x, wid = tid >> 5, lane = tid & 31;
    const int gid = lane >> 2, tid4 = lane & 3;
    const int wm0 = (wid & 3) * 32, wn0 = (wid >> 2) * 64;
    const int v0 = blockIdx.x * 128;

    float st1[16] = {}, st2[16] = {};

    // B tile once: 128 rows x 200 k (25 uint4 per row)
    for (int i = tid; i < 128 * 25; i += 256) {
        int row = i / 25, kv = i % 25;
        *(uint4*)&Bs[row * P3 + kv * 8] = *(const uint4*)&g_betaT[(v0 + row) * KK + kv * 8];
    }

    for (int mt = 0; mt < 8; mt++) {
        const int m0 = mt * 128;
        __syncthreads();
        for (int i = tid; i < 128 * 25; i += 256) {
            int row = i / 25, kv = i % 25;
            *(uint4*)&As[row * P3 + kv * 8] = *(const uint4*)&g_thetab[(m0 + row) * KK + kv * 8];
        }
        __syncthreads();

        float c[2][8][4] = {};
        mma_steps<P3, 12>(As, Bs, wm0, wn0, gid, tid4, c);

        // k8 remainder: k = 192..199 (validated: bit-identical rel_err in R8)
        {
            const int k0r = 192 + 2 * tid4;
            #pragma unroll
            for (int mt2 = 0; mt2 < 2; mt2++) {
                int r = wm0 + mt2 * 16 + gid;
                uint32_t a0 = *(const uint32_t*)&As[r * P3 + k0r];
                uint32_t a1 = *(const uint32_t*)&As[(r + 8) * P3 + k0r];
                #pragma unroll
                for (int nt = 0; nt < 8; nt++) {
                    uint32_t b0 = *(const uint32_t*)&Bs[(wn0 + nt * 8 + gid) * P3 + k0r];
                    asm volatile(
                        "mma.sync.aligned.m16n8k8.row.col.f32.f16.f16.f32 "
                        "{%0,%1,%2,%3}, {%4,%5}, {%6}, {%0,%1,%2,%3};"
                        : "+f"(c[mt2][nt][0]), "+f"(c[mt2][nt][1]),
                          "+f"(c[mt2][nt][2]), "+f"(c[mt2][nt][3])
                        : "r"(a0), "r"(a1), "r"(b0));
                }
            }
        }

        #pragma unroll
        for (int mt2 = 0; mt2 < 2; mt2++) {
            int r0 = m0 + wm0 + mt2 * 16 + gid;
            float s0 = g_mrow[r0];
            float s1 = g_mrow[r0 + 8];
            #pragma unroll
            for (int nt = 0; nt < 8; nt++) {
                int v = v0 + wn0 + nt * 8 + 2 * tid4;
                float y00 = c[mt2][nt][0], y01 = c[mt2][nt][1];
                float y10 = c[mt2][nt][2], y11 = c[mt2][nt][3];
                *(__half2*)&g_y[(size_t)r0 * VP + v]       = __floats2half2_rn(y00, y01);
                *(__half2*)&g_y[(size_t)(r0 + 8) * VP + v] = __floats2half2_rn(y10, y11);
                float t00 = s0 * y00, t01 = s0 * y01;
                float t10 = s1 * y10, t11 = s1 * y11;
                st1[nt * 2]     += t00 + t10;
                st2[nt * 2]     += t00 * t00 + t10 * t10;
                st1[nt * 2 + 1] += t01 + t11;
                st2[nt * 2 + 1] += t01 * t01 + t11 * t11;
            }
        }
    }

    // deterministic stats reduction: gid (shfl) -> warps (smem)
    #pragma unroll
    for (int i = 0; i < 16; i++) {
        #pragma unroll
        for (int off = 16; off >= 4; off >>= 1) {
            st1[i] += __shfl_down_sync(0xffffffffu, st1[i], off);
            st2[i] += __shfl_down_sync(0xffffffffu, st2[i], off);
        }
    }
    if (lane < 4) {
        float* p = &sred[(wid * 4 + lane) * 32];
        #pragma unroll
        for (int i = 0; i < 16; i++) { p[i * 2] = st1[i]; p[i * 2 + 1] = st2[i]; }
    }
    __syncthreads();
    if (tid < 128) {
        int col = tid;
        int grp = col >> 6, nt = (col & 63) >> 3, t4 = (col & 7) >> 1, j = col & 1;
        int idx = nt * 2 + j;
        float s1 = 0.f, s2 = 0.f;
        #pragma unroll
        for (int w2 = 0; w2 < 4; w2++) {
            const float* p = &sred[((4 * grp + w2) * 4 + t4) * 32];
            s1 += p[idx * 2];
            s2 += p[idx * 2 + 1];
        }
        int vg = v0 + col;
        if (vg < VV) {
            float m = s1 * (1.f / BB);
            float var = fmaxf(s2 * (1.f / BB) - m * m, 0.f);
            float a = bn_beta_g[vg] * rsqrtf(var + BN_EPS);
            g_av[vg] = a;
            g_cv[vg] = bn_beta_b[vg] - a * m;
        }
    }
}

// ---------------- final: lse + histogram dot, 8 rows per CTA --------------------
__global__ void __launch_bounds__(256) k_final(float* __restrict__ out) {
    const int b0 = blockIdx.x * 8;
    const int tid = threadIdx.x;
    float se[8] = {}, dot[8] = {};
    float sr[8];
    #pragma unroll
    for (int r = 0; r < 8; r++) sr[r] = g_mrow[b0 + r];

    for (int v0 = 0; v0 < VP; v0 += 512) {
        int v = v0 + 2 * tid;
        if (v >= VV) continue;   // VV even, v even -> pair fully valid or fully skipped
        float a0 = g_av[v],  a1 = g_av[v + 1];
        float c0 = g_cv[v],  c1 = g_cv[v + 1];
        float n0 = (float)g_cnt[v], n1 = (float)g_cnt[v + 1];
        #pragma unroll
        for (int r = 0; r < 8; r++) {
            float2 yf = __half22float2(*(const __half2*)&g_y[(size_t)(b0 + r) * VP + v]);
            float nl0 = fmaf(a0, sr[r] * yf.x, c0);
            float nl1 = fmaf(a1, sr[r] * yf.y, c1);
            se[r]  += expf(nl0) + expf(nl1);
            dot[r] += n0 * nl0 + n1 * nl1;
        }
    }

    #pragma unroll
    for (int r = 0; r < 8; r++) {
        #pragma unroll
        for (int off = 16; off; off >>= 1) {
            se[r]  += __shfl_down_sync(0xffffffffu, se[r],  off);
            dot[r] += __shfl_down_sync(0xffffffffu, dot[r], off);
        }
    }
    __shared__ double sdr[8][8][2];
    int lane = tid & 31, w = tid >> 5;
    if (!lane) {
        #pragma unroll
        for (int r = 0; r < 8; r++) { sdr[w][r][0] = (double)se[r]; sdr[w][r][1] = (double)dot[r]; }
    }
    __syncthreads();
    if (tid < 8) {
        double S = 0.0, D = 0.0;
        for (int w2 = 0; w2 < 8; w2++) { S += sdr[w2][tid][0]; D += sdr[w2][tid][1]; }
        out[b0 + tid] = (float)(D - (double)TT * log(S));
    }
}

// ---------------- launch --------------------------------------------------------
extern "C" void kernel_launch(void* const* d_in, const int* in_sizes, int n_in,
                              void* d_out, int out_size) {
    const float* bows      = (const float*)d_in[0];
    const float* eps       = (const float*)d_in[1];
    const int*   toks      = (const int*)  d_in[2];
    const float* fc1_w     = (const float*)d_in[3];
    const float* fc1_b     = (const float*)d_in[4];
    const float* fc2_w     = (const float*)d_in[5];
    const float* fc2_b     = (const float*)d_in[6];
    const float* mu_w      = (const float*)d_in[7];
    const float* bn_mu_g   = (const float*)d_in[9];
    const float* bn_mu_b   = (const float*)d_in[10];
    const float* sig_w     = (const float*)d_in[11];
    const float* bn_sig_g  = (const float*)d_in[13];
    const float* bn_sig_b  = (const float*)d_in[14];
    const float* beta_w    = (const float*)d_in[15];
    const float* bn_beta_g = (const float*)d_in[17];
    const float* bn_beta_b = (const float*)d_in[18];
    float* out = (float*)d_out;

    const int g1_smem = 4 * G1_BUF * (int)sizeof(__half);       // 73728
    cudaFuncSetAttribute(k_gemm1, cudaFuncAttributeMaxDynamicSharedMemorySize, g1_smem);
    cudaFuncSetAttribute(k_gemm3, cudaFuncAttributeMaxDynamicSharedMemorySize, G3_SMEM);

    // k_gemm1 is deliberately the 4th launch: the harness's ncu capture
    // profiles launch #4, giving us the GEMM1 profile this round.
    k_zero<<<(VV + 255) / 256, 256>>>();
    k_hist<<<(TT + 255) / 256, 256>>>(toks);
    k_cvt_fc1<<<dim3(KP1 / 32, 4), dim3(32, 8)>>>(fc1_w);
    k_gemm1<<<dim3(8, SPLITS), 256, g1_smem>>>(bows);
    k_cvt_beta<<<dim3(1563, 7), dim3(32, 8)>>>(beta_w);
    k_red1<<<(BB * HH + 255) / 256, 256>>>(fc1_b);
    k_mid<<<BB / 16, 256>>>(fc2_w, fc2_b, mu_w, sig_w);
    k_theta<<<KK, 256>>>(eps, bn_mu_g, bn_mu_b, bn_sig_g, bn_sig_b);
    k_rowexp<<<BB, 64>>>();
    k_gemm3<<<VT3, 256, G3_SMEM>>>(bn_beta_g, bn_beta_b);
    k_final<<<128, 256>>>(out);
}